// round 12
// baseline (speedup 1.0000x reference)
#include <cuda_runtime.h>
#include <cuda_fp16.h>
#include <math.h>
#include <stdint.h>

#define N_TOK 4096
#define D_DIM 1024
#define E_NUM 8
#define F_DIM 4096
#define K_CAP 512

// -------- persistent scratch (device globals; no allocations allowed) --------
__device__ float g_probT[E_NUM * N_TOK];
__device__ int   g_routes[E_NUM * K_CAP];
__device__ float g_vals[E_NUM * K_CAP];
__device__ __align__(16) __half g_x16[(size_t)E_NUM * K_CAP * D_DIM];
__device__ __align__(16) __half g_h16[(size_t)E_NUM * K_CAP * F_DIM];
__device__ __align__(16) __half g_w1[(size_t)E_NUM * F_DIM * D_DIM];   // W1^T [E][F][D]
__device__ __align__(16) __half g_w2[(size_t)E_NUM * D_DIM * F_DIM];   // W2^T [E][D][F]

// ---------------- helpers ----------------
__device__ __forceinline__ uint32_t smem_u32(const void* p) {
    uint32_t a;
    asm("{ .reg .u64 t; cvta.to.shared.u64 t, %1; cvt.u32.u64 %0, t; }" : "=r"(a) : "l"(p));
    return a;
}
#define CP16(dst, src) \
    asm volatile("cp.async.cg.shared.global [%0], [%1], 16;" :: "r"(dst), "l"(src))
#define CP_COMMIT() asm volatile("cp.async.commit_group;" ::: "memory")
#define CP_WAIT(n)  asm volatile("cp.async.wait_group %0;" :: "n"(n) : "memory")

__device__ __forceinline__ void mma16816(float* c, const uint32_t* a, const uint32_t* b) {
    asm volatile(
        "mma.sync.aligned.m16n8k16.row.col.f32.f16.f16.f32 "
        "{%0,%1,%2,%3}, {%4,%5,%6,%7}, {%8,%9}, {%0,%1,%2,%3};"
        : "+f"(c[0]), "+f"(c[1]), "+f"(c[2]), "+f"(c[3])
        : "r"(a[0]), "r"(a[1]), "r"(a[2]), "r"(a[3]), "r"(b[0]), "r"(b[1]));
}
__device__ __forceinline__ void ldsm4(uint32_t* d, uint32_t addr) {
    asm volatile("ldmatrix.sync.aligned.m8n8.x4.shared.b16 {%0,%1,%2,%3}, [%4];"
                 : "=r"(d[0]), "=r"(d[1]), "=r"(d[2]), "=r"(d[3]) : "r"(addr));
}
__device__ __forceinline__ void red2(float* gptr, float v0, float v1) {
    asm volatile("red.global.add.v2.f32 [%0], {%1, %2};"
                 :: "l"(gptr), "f"(v0), "f"(v1) : "memory");
}
__device__ __forceinline__ float gelu_tanh(float v) {
    float u = 0.7978845608028654f * (v + 0.044715f * v * v * v);
    float t;
    asm("tanh.approx.f32 %0, %1;" : "=f"(t) : "f"(u));
    return 0.5f * v * (1.0f + t);
}
__device__ __forceinline__ uint32_t pack_h2(float a, float b) {
    __half2 t = __floats2half2_rn(a, b);
    return *(uint32_t*)&t;
}

// generic 32x32 transpose+convert tile: src fp32 [R][C] -> dst fp16 [C][R], 256 threads
__device__ __forceinline__ void conv_tile(const float* __restrict__ src, __half* __restrict__ dst,
                                          int R, int C, int ltile, float* tt, int tid) {
    const int tx = tid & 31, ty = tid >> 5;
    const int e = ltile >> 12;               // 4096 tiles per expert
    const int rem = ltile & 4095;
    const int ctiles = C >> 5;
    const int c0 = (rem % ctiles) << 5;
    const int r0 = (rem / ctiles) << 5;
    const size_t mat = (size_t)e * D_DIM * F_DIM;
#pragma unroll
    for (int j = ty; j < 32; j += 8)
        tt[j * 33 + tx] = src[mat + (size_t)(r0 + j) * C + c0 + tx];
    __syncthreads();
#pragma unroll
    for (int j = ty; j < 32; j += 8)
        dst[mat + (size_t)(c0 + j) * R + r0 + tx] = __float2half_rn(tt[tx * 33 + j]);
}

// ============ phase 1: gating (0..511) || zero (512..4607) || conv W1 (4608..37375) ====
__global__ void phase1_kernel(const float* __restrict__ x,
                              const float* __restrict__ Ws,
                              const float* __restrict__ bs,
                              float4* __restrict__ out,
                              const float* __restrict__ W1) {
    __shared__ float tt[32 * 33];
    const int tid = threadIdx.x;
    const int bx = blockIdx.x;
    if (bx >= 4608) {
        conv_tile(W1, g_w1, D_DIM, F_DIM, bx - 4608, tt, tid);   // W1 [D][F] -> g_w1 [F][D]
        return;
    }
    if (bx >= 512) {
        out[(bx - 512) * 256 + tid] = make_float4(0.f, 0.f, 0.f, 0.f);
        return;
    }
    const int lane = tid & 31, ty = tid >> 5;
    int t = bx * 8 + ty;
    const float* xr = x + (size_t)t * D_DIM;
    float acc[E_NUM];
#pragma unroll
    for (int e = 0; e < E_NUM; e++) acc[e] = 0.f;
    for (int i = lane; i < D_DIM; i += 32) {
        float xi = xr[i];
        const float* w = Ws + (size_t)i * E_NUM;
#pragma unroll
        for (int e = 0; e < E_NUM; e++) acc[e] += xi * w[e];
    }
#pragma unroll
    for (int e = 0; e < E_NUM; e++)
#pragma unroll
        for (int off = 16; off > 0; off >>= 1)
            acc[e] += __shfl_xor_sync(0xFFFFFFFFu, acc[e], off);
    if (lane == 0) {
        float mx = -1e30f;
#pragma unroll
        for (int e = 0; e < E_NUM; e++) { acc[e] += bs[e]; mx = fmaxf(mx, acc[e]); }
        float s = 0.f;
#pragma unroll
        for (int e = 0; e < E_NUM; e++) { acc[e] = __expf(acc[e] - mx); s += acc[e]; }
        float inv = 1.f / s;
#pragma unroll
        for (int e = 0; e < E_NUM; e++) g_probT[e * N_TOK + t] = acc[e] * inv;
    }
}

// ============ phase 2: per-expert top-k (bitonic), 8 blocks x 512 thr ============
__global__ void topk_kernel() {
    __shared__ unsigned long long keys[N_TOK];
    const int e = blockIdx.x;
    const int tid = threadIdx.x;
    for (int i = tid; i < N_TOK; i += 512) {
        unsigned vb = __float_as_uint(g_probT[e * N_TOK + i]);
        keys[i] = ((unsigned long long)vb << 32) | (unsigned)(0xFFFFFFFFu - (unsigned)i);
    }
    __syncthreads();
    for (int k = 2; k <= N_TOK; k <<= 1) {
        for (int j = k >> 1; j > 0; j >>= 1) {
            for (int i = tid; i < N_TOK; i += 512) {
                int ixj = i ^ j;
                if (ixj > i) {
                    unsigned long long a = keys[i], b = keys[ixj];
                    bool up = ((i & k) == 0);
                    if (up ? (a > b) : (a < b)) { keys[i] = b; keys[ixj] = a; }
                }
            }
            __syncthreads();
        }
    }
    for (int i = tid; i < K_CAP; i += 512) {
        unsigned long long kk = keys[N_TOK - K_CAP + i];
        g_vals[e * K_CAP + i]   = __uint_as_float((unsigned)(kk >> 32));
        g_routes[e * K_CAP + i] = (int)(0xFFFFFFFFu - (unsigned)(kk & 0xFFFFFFFFu));
    }
}

// ---------------- gather -> fp16 ----------------
__global__ void gather_kernel(const float* __restrict__ x) {
    int row = blockIdx.x;
    int tok = g_routes[row];
    const float4* src = (const float4*)(x + (size_t)tok * D_DIM);
    float4 v = src[threadIdx.x];
    uint2 h = make_uint2(pack_h2(v.x, v.y), pack_h2(v.z, v.w));
    ((uint2*)(g_x16 + (size_t)row * D_DIM))[threadIdx.x] = h;
}

// ---------------- fp16 single-pass HMMA grouped GEMM mainloop (shared) ----------------
#define STAGE_BYTES 16384     // A 8K | B 8K
#define NSTAGES 5
#define SMEM_BYTES (NSTAGES * STAGE_BYTES)

template <int K>
__device__ __forceinline__ void gemm_mainloop(
    const __half* __restrict__ Ag, const __half* __restrict__ Bg,
    int m0, int n0, uint32_t sb, char* sm, int tid, int wid, int lane,
    float acc[4][4][4])
{
    constexpr int ITERS = K / 32;
    const int wm = (wid & 1) * 64, wn = (wid >> 1) * 32;
    const int mi = lane >> 3, j = lane & 7;
    uint32_t a_rowterm[4], a_xr[4];
    const int a_kbh = mi >> 1;
#pragma unroll
    for (int mt = 0; mt < 4; mt++) {
        int row = wm + mt * 16 + ((mi & 1) << 3) + j;
        a_rowterm[mt] = row * 64;
        a_xr[mt] = (row >> 1) & 3;
    }
    uint32_t b_rowterm[2], b_xr[2];
    const int b_kbh = mi & 1;
#pragma unroll
    for (int ntp = 0; ntp < 2; ntp++) {
        int row = wn + ntp * 16 + ((mi >> 1) << 3) + j;
        b_rowterm[ntp] = row * 64;
        b_xr[ntp] = (row >> 1) & 3;
    }

    auto load_stage = [&](int stage, int k0) {
        const uint32_t base = sb + stage * STAGE_BYTES;
#pragma unroll
        for (int jj = 0; jj < 2; jj++) {
            int cid = tid + jj * 256;
            int row = cid >> 2, kb = cid & 3;
            int pk = kb ^ ((row >> 1) & 3);
            uint32_t doff = row * 64 + pk * 16;
            size_t aoff = (size_t)(m0 + row) * K + k0 + kb * 8;
            size_t boff = (size_t)(n0 + row) * K + k0 + kb * 8;
            CP16(base + doff,        Ag + aoff);
            CP16(base + 8192 + doff, Bg + boff);
        }
        CP_COMMIT();
    };

    load_stage(0, 0);
    load_stage(1, 32);
    load_stage(2, 64);
    load_stage(3, 96);

    for (int it = 0; it < ITERS; it++) {
        const int s = it % NSTAGES;
        CP_WAIT(3);
        __syncthreads();
        if (it + 4 < ITERS) load_stage((it + 4) % NSTAGES, (it + 4) * 32);

        const uint32_t baseA = sb + s * STAGE_BYTES;
        const uint32_t baseB = baseA + 8192;

#pragma unroll
        for (int sub = 0; sub < 2; sub++) {
            uint32_t bf[2][4];
#pragma unroll
            for (int ntp = 0; ntp < 2; ntp++) {
                uint32_t off = b_rowterm[ntp] + ((((uint32_t)(2 * sub + b_kbh)) ^ b_xr[ntp]) << 4);
                ldsm4(bf[ntp], baseB + off);
            }
#pragma unroll
            for (int mt = 0; mt < 4; mt++) {
                uint32_t ah[4];
                uint32_t off = a_rowterm[mt] + ((((uint32_t)(2 * sub + a_kbh)) ^ a_xr[mt]) << 4);
                ldsm4(ah, baseA + off);
#pragma unroll
                for (int nt = 0; nt < 4; nt++) {
                    const uint32_t* b2 = &bf[nt >> 1][(nt & 1) * 2];
                    mma16816(acc[mt][nt], ah, b2);
                }
            }
        }
        __syncthreads();
    }
}

// ---- GEMM1 (x16 @ w1 -> gelu -> h16) fused with W2 transpose+convert blocks ----
__global__ __launch_bounds__(256, 2)
void moe_mma0(const float* __restrict__ biasAll, const float* __restrict__ W2src) {
    extern __shared__ char sm[];
    const int tid = threadIdx.x;
    const int bx = blockIdx.x;

    if (bx >= 1024) {                 // conv W2: [F][D] -> g_w2 [D][F]
        conv_tile(W2src, g_w2, F_DIM, D_DIM, bx - 1024, (float*)sm, tid);
        return;
    }

    const uint32_t sb = smem_u32(sm);
    const int wid = tid >> 5, lane = tid & 31;
    const int e = bx >> 7, m0 = ((bx >> 5) & 3) * 128, n0 = (bx & 31) * 128;
    const int wm = (wid & 1) * 64, wn = (wid >> 1) * 32;

    const __half* Ag = g_x16 + (size_t)e * K_CAP * D_DIM;
    const __half* Bg = g_w1 + (size_t)e * (size_t)F_DIM * D_DIM;

    float acc[4][4][4];
#pragma unroll
    for (int i = 0; i < 4; i++)
#pragma unroll
        for (int jj = 0; jj < 4; jj++)
#pragma unroll
            for (int q = 0; q < 4; q++) acc[i][jj][q] = 0.f;

    gemm_mainloop<D_DIM>(Ag, Bg, m0, n0, sb, sm, tid, wid, lane, acc);

    const int gid = lane >> 2, tig = lane & 3;
    const float* bias = biasAll + (size_t)e * F_DIM;
#pragma unroll
    for (int mt = 0; mt < 4; mt++) {
#pragma unroll
        for (int half = 0; half < 2; half++) {
            int row = m0 + wm + mt * 16 + gid + half * 8;
            __half* ph = g_h16 + ((size_t)e * K_CAP + row) * F_DIM;
#pragma unroll
            for (int nt = 0; nt < 4; nt++) {
                int col = n0 + wn + nt * 8 + tig * 2;
                float v0 = gelu_tanh(acc[mt][nt][half * 2 + 0] + bias[col]);
                float v1 = gelu_tanh(acc[mt][nt][half * 2 + 1] + bias[col + 1]);
                *(uint32_t*)(ph + col) = pack_h2(v0, v1);
            }
        }
    }
}

// ---- GEMM2 (h16 @ w2 -> *val -> scatter-add out) ----
__global__ __launch_bounds__(256, 2)
void moe_mma1(const float* __restrict__ biasAll, float* __restrict__ outFinal) {
    extern __shared__ char sm[];
    const uint32_t sb = smem_u32(sm);
    const int tid = threadIdx.x, wid = tid >> 5, lane = tid & 31;
    const int e = blockIdx.z, m0 = blockIdx.y * 128, n0 = blockIdx.x * 128;
    const int wm = (wid & 1) * 64, wn = (wid >> 1) * 32;

    const __half* Ag = g_h16 + (size_t)e * K_CAP * F_DIM;
    const __half* Bg = g_w2 + (size_t)e * (size_t)D_DIM * F_DIM;

    float acc[4][4][4];
#pragma unroll
    for (int i = 0; i < 4; i++)
#pragma unroll
        for (int jj = 0; jj < 4; jj++)
#pragma unroll
            for (int q = 0; q < 4; q++) acc[i][jj][q] = 0.f;

    gemm_mainloop<F_DIM>(Ag, Bg, m0, n0, sb, sm, tid, wid, lane, acc);

    const int gid = lane >> 2, tig = lane & 3;
    const float* bias = biasAll + (size_t)e * D_DIM;
#pragma unroll
    for (int mt = 0; mt < 4; mt++) {
#pragma unroll
        for (int half = 0; half < 2; half++) {
            int row = m0 + wm + mt * 16 + gid + half * 8;
            const int tok = g_routes[e * K_CAP + row];
            const float scale = g_vals[e * K_CAP + row];
            float* orow = outFinal + (size_t)tok * D_DIM;
#pragma unroll
            for (int nt = 0; nt < 4; nt++) {
                int col = n0 + wn + nt * 8 + tig * 2;
                float v0 = (acc[mt][nt][half * 2 + 0] + bias[col]) * scale;
                float v1 = (acc[mt][nt][half * 2 + 1] + bias[col + 1]) * scale;
                red2(orow + col, v0, v1);
            }
        }
    }
}

extern "C" void kernel_launch(void* const* d_in, const int* in_sizes, int n_in,
                              void* d_out, int out_size) {
    const float* x  = (const float*)d_in[0];
    const float* Ws = (const float*)d_in[1];
    const float* bs = (const float*)d_in[2];
    const float* W1 = (const float*)d_in[3];
    const float* b1 = (const float*)d_in[4];
    const float* W2 = (const float*)d_in[5];
    const float* b2 = (const float*)d_in[6];
    float* out = (float*)d_out;

    cudaFuncSetAttribute(moe_mma0, cudaFuncAttributeMaxDynamicSharedMemorySize, SMEM_BYTES);
    cudaFuncSetAttribute(moe_mma1, cudaFuncAttributeMaxDynamicSharedMemorySize, SMEM_BYTES);

    // phase 1: gating (512) || zero (4096) || conv W1 (32768)
    phase1_kernel<<<512 + 4096 + 32768, 256>>>(x, Ws, bs, (float4*)out, W1);
    // phase 2: top-k
    topk_kernel<<<E_NUM, 512>>>();
    gather_kernel<<<E_NUM * K_CAP, 256>>>(x);
    // GEMM1 (1024 blocks) || conv W2 (32768 blocks)
    moe_mma0<<<1024 + 32768, 256, SMEM_BYTES>>>(b1, W2);
    moe_mma1<<<dim3(D_DIM / 128, K_CAP / 128, E_NUM), 256, SMEM_BYTES>>>(b2, out);
}

// round 14
// speedup vs baseline: 1.3561x; 1.3561x over previous
#include <cuda_runtime.h>
#include <cuda_fp16.h>
#include <math.h>
#include <stdint.h>

#define N_TOK 4096
#define D_DIM 1024
#define E_NUM 8
#define F_DIM 4096
#define K_CAP 512

// -------- persistent scratch (device globals; no allocations allowed) --------
__device__ float g_probT[E_NUM * N_TOK];
__device__ int   g_routes[E_NUM * K_CAP];
__device__ float g_vals[E_NUM * K_CAP];
__device__ __align__(16) __half g_x16[(size_t)E_NUM * K_CAP * D_DIM];
__device__ __align__(16) __half g_h16[(size_t)E_NUM * K_CAP * F_DIM];
__device__ __align__(16) __half g_w1c[(size_t)E_NUM * D_DIM * F_DIM];  // W1 fp16, natural [E][D][F]
__device__ __align__(16) __half g_w2c[(size_t)E_NUM * F_DIM * D_DIM];  // W2 fp16, natural [E][F][D]

// ---------------- helpers ----------------
__device__ __forceinline__ uint32_t smem_u32(const void* p) {
    uint32_t a;
    asm("{ .reg .u64 t; cvta.to.shared.u64 t, %1; cvt.u32.u64 %0, t; }" : "=r"(a) : "l"(p));
    return a;
}
#define CP16(dst, src) \
    asm volatile("cp.async.cg.shared.global [%0], [%1], 16;" :: "r"(dst), "l"(src))
#define CP_COMMIT() asm volatile("cp.async.commit_group;" ::: "memory")
#define CP_WAIT(n)  asm volatile("cp.async.wait_group %0;" :: "n"(n) : "memory")

__device__ __forceinline__ void mma16816(float* c, const uint32_t* a, const uint32_t* b) {
    asm volatile(
        "mma.sync.aligned.m16n8k16.row.col.f32.f16.f16.f32 "
        "{%0,%1,%2,%3}, {%4,%5,%6,%7}, {%8,%9}, {%0,%1,%2,%3};"
        : "+f"(c[0]), "+f"(c[1]), "+f"(c[2]), "+f"(c[3])
        : "r"(a[0]), "r"(a[1]), "r"(a[2]), "r"(a[3]), "r"(b[0]), "r"(b[1]));
}
__device__ __forceinline__ void ldsm4(uint32_t* d, uint32_t addr) {
    asm volatile("ldmatrix.sync.aligned.m8n8.x4.shared.b16 {%0,%1,%2,%3}, [%4];"
                 : "=r"(d[0]), "=r"(d[1]), "=r"(d[2]), "=r"(d[3]) : "r"(addr));
}
__device__ __forceinline__ void ldsm4t(uint32_t* d, uint32_t addr) {
    asm volatile("ldmatrix.sync.aligned.m8n8.x4.trans.shared.b16 {%0,%1,%2,%3}, [%4];"
                 : "=r"(d[0]), "=r"(d[1]), "=r"(d[2]), "=r"(d[3]) : "r"(addr));
}
__device__ __forceinline__ void red2(float* gptr, float v0, float v1) {
    asm volatile("red.global.add.v2.f32 [%0], {%1, %2};"
                 :: "l"(gptr), "f"(v0), "f"(v1) : "memory");
}
__device__ __forceinline__ float gelu_tanh(float v) {
    float u = 0.7978845608028654f * (v + 0.044715f * v * v * v);
    float t;
    asm("tanh.approx.f32 %0, %1;" : "=f"(t) : "f"(u));
    return 0.5f * v * (1.0f + t);
}
__device__ __forceinline__ uint32_t pack_h2(float a, float b) {
    __half2 t = __floats2half2_rn(a, b);
    return *(uint32_t*)&t;
}
// streaming fp32 -> fp16 convert, 1 float4 -> 1 uint2
__device__ __forceinline__ void conv_f4(const float4* __restrict__ src, uint2* __restrict__ dst,
                                        size_t idx) {
    float4 v = src[idx];
    dst[idx] = make_uint2(pack_h2(v.x, v.y), pack_h2(v.z, v.w));
}

// ===== phase 1: gating (0..511) || zero (512..4607) || conv W1 (4608..8703) =====
// conv W1: 8,388,608 float4 over 4096 blocks x 256 thr x 8 f4
__global__ void phase1_kernel(const float* __restrict__ x,
                              const float* __restrict__ Ws,
                              const float* __restrict__ bs,
                              float4* __restrict__ out,
                              const float4* __restrict__ W1s) {
    const int tid = threadIdx.x;
    const int bx = blockIdx.x;
    if (bx >= 4608) {
        const size_t base = (size_t)(bx - 4608) * 2048 + tid;
#pragma unroll
        for (int k = 0; k < 8; k++)
            conv_f4(W1s, (uint2*)g_w1c, base + k * 256);
        return;
    }
    if (bx >= 512) {
        out[(bx - 512) * 256 + tid] = make_float4(0.f, 0.f, 0.f, 0.f);
        return;
    }
    const int lane = tid & 31, ty = tid >> 5;
    int t = bx * 8 + ty;
    const float* xr = x + (size_t)t * D_DIM;
    float acc[E_NUM];
#pragma unroll
    for (int e = 0; e < E_NUM; e++) acc[e] = 0.f;
    for (int i = lane; i < D_DIM; i += 32) {
        float xi = xr[i];
        const float* w = Ws + (size_t)i * E_NUM;
#pragma unroll
        for (int e = 0; e < E_NUM; e++) acc[e] += xi * w[e];
    }
#pragma unroll
    for (int e = 0; e < E_NUM; e++)
#pragma unroll
        for (int off = 16; off > 0; off >>= 1)
            acc[e] += __shfl_xor_sync(0xFFFFFFFFu, acc[e], off);
    if (lane == 0) {
        float mx = -1e30f;
#pragma unroll
        for (int e = 0; e < E_NUM; e++) { acc[e] += bs[e]; mx = fmaxf(mx, acc[e]); }
        float s = 0.f;
#pragma unroll
        for (int e = 0; e < E_NUM; e++) { acc[e] = __expf(acc[e] - mx); s += acc[e]; }
        float inv = 1.f / s;
#pragma unroll
        for (int e = 0; e < E_NUM; e++) g_probT[e * N_TOK + t] = acc[e] * inv;
    }
}

// ===== phase 2: topk (blocks 0..7) || conv W2 (blocks 8..2055, 512 thr x 8 f4) =====
__global__ void prep_kernel(const float4* __restrict__ W2s) {
    __shared__ unsigned long long keys[N_TOK];
    const int tid = threadIdx.x;
    if (blockIdx.x >= 8) {
        const size_t base = (size_t)(blockIdx.x - 8) * 4096 + tid;
#pragma unroll
        for (int k = 0; k < 8; k++)
            conv_f4(W2s, (uint2*)g_w2c, base + k * 512);
        return;
    }
    const int e = blockIdx.x;
    for (int i = tid; i < N_TOK; i += 512) {
        unsigned vb = __float_as_uint(g_probT[e * N_TOK + i]);
        keys[i] = ((unsigned long long)vb << 32) | (unsigned)(0xFFFFFFFFu - (unsigned)i);
    }
    __syncthreads();
    for (int k = 2; k <= N_TOK; k <<= 1) {
        for (int j = k >> 1; j > 0; j >>= 1) {
            for (int i = tid; i < N_TOK; i += 512) {
                int ixj = i ^ j;
                if (ixj > i) {
                    unsigned long long a = keys[i], b = keys[ixj];
                    bool up = ((i & k) == 0);
                    if (up ? (a > b) : (a < b)) { keys[i] = b; keys[ixj] = a; }
                }
            }
            __syncthreads();
        }
    }
    for (int i = tid; i < K_CAP; i += 512) {
        unsigned long long kk = keys[N_TOK - K_CAP + i];
        g_vals[e * K_CAP + i]   = __uint_as_float((unsigned)(kk >> 32));
        g_routes[e * K_CAP + i] = (int)(0xFFFFFFFFu - (unsigned)(kk & 0xFFFFFFFFu));
    }
}

// ---------------- gather -> fp16 ----------------
__global__ void gather_kernel(const float* __restrict__ x) {
    int row = blockIdx.x;
    int tok = g_routes[row];
    const float4* src = (const float4*)(x + (size_t)tok * D_DIM);
    float4 v = src[threadIdx.x];
    uint2 h = make_uint2(pack_h2(v.x, v.y), pack_h2(v.z, v.w));
    ((uint2*)(g_x16 + (size_t)row * D_DIM))[threadIdx.x] = h;
}

// ---------------- fp16 HMMA grouped GEMM, B in NATURAL [K][N] layout ----------------
// A smem: [128m][32k] 64B rows, xor swizzle (unchanged).
// B smem: [32k][128n] 256B rows; chunk c (16B) at row k placed at (c ^ (k&15)).
//   STS: warp = 2 rows x 16 chunks, 8-lane phase covers 8 distinct 16B banks. OK.
//   ldsm4t: 8 lanes read 8 rows (256B stride) same c -> (c^rs) distinct mod 8. OK.
#define STAGE_BYTES 16384     // A 8K | B 8K
#define NSTAGES 5
#define SMEM_BYTES (NSTAGES * STAGE_BYTES)

template <int K, int NCT>
__device__ __forceinline__ void gemm_mainloop(
    const __half* __restrict__ Ag, const __half* __restrict__ Bg,
    int m0, int n0, uint32_t sb, int tid, int wid, int lane,
    float acc[4][4][4])
{
    constexpr int ITERS = K / 32;
    const int wm = (wid & 1) * 64, wn = (wid >> 1) * 32;
    const int mi = lane >> 3, j = lane & 7;

    // A ldmatrix addressing (unchanged)
    uint32_t a_rowterm[4], a_xr[4];
    const int a_kbh = mi >> 1;
#pragma unroll
    for (int mt = 0; mt < 4; mt++) {
        int row = wm + mt * 16 + ((mi & 1) << 3) + j;
        a_rowterm[mt] = row * 64;
        a_xr[mt] = (row >> 1) & 3;
    }
    // B trans-ldmatrix addressing: row-in-sub rs, chunk base cb
    const int b_rs = ((mi & 1) << 3) + j;          // 0..15
    const int b_cb = (wn >> 3) + (mi >> 1);        // chunk index

    auto load_stage = [&](int stage, int k0) {
        const uint32_t base = sb + stage * STAGE_BYTES;
#pragma unroll
        for (int jj = 0; jj < 2; jj++) {
            int cid = tid + jj * 256;
            // A chunk
            int ar = cid >> 2, akb = cid & 3;
            uint32_t adoff = ar * 64 + ((akb ^ ((ar >> 1) & 3)) << 4);
            CP16(base + adoff, Ag + (size_t)(m0 + ar) * K + k0 + akb * 8);
            // B chunk (natural layout)
            int bk = cid >> 4, bc = cid & 15;
            uint32_t bdoff = bk * 256 + ((bc ^ (bk & 15)) << 4);
            CP16(base + 8192 + bdoff, Bg + (size_t)(k0 + bk) * NCT + n0 + bc * 8);
        }
        CP_COMMIT();
    };

    load_stage(0, 0);
    load_stage(1, 32);
    load_stage(2, 64);
    load_stage(3, 96);

    for (int it = 0; it < ITERS; it++) {
        const int s = it % NSTAGES;
        CP_WAIT(3);
        __syncthreads();
        if (it + 4 < ITERS) load_stage((it + 4) % NSTAGES, (it + 4) * 32);

        const uint32_t baseA = sb + s * STAGE_BYTES;
        const uint32_t baseB = baseA + 8192;

#pragma unroll
        for (int sub = 0; sub < 2; sub++) {
            uint32_t bf[2][4];
#pragma unroll
            for (int ntp = 0; ntp < 2; ntp++) {
                int c = b_cb + 2 * ntp;
                uint32_t off = sub * 4096 + b_rs * 256 + (((c ^ b_rs) & 15) << 4);
                ldsm4t(bf[ntp], baseB + off);
            }
#pragma unroll
            for (int mt = 0; mt < 4; mt++) {
                uint32_t ah[4];
                uint32_t off = a_rowterm[mt] + ((((uint32_t)(2 * sub + a_kbh)) ^ a_xr[mt]) << 4);
                ldsm4(ah, baseA + off);
#pragma unroll
                for (int nt = 0; nt < 4; nt++) {
                    const uint32_t* b2 = &bf[nt >> 1][(nt & 1) * 2];
                    mma16816(acc[mt][nt], ah, b2);
                }
            }
        }
        __syncthreads();
    }
}

// ---- GEMM1: x16 @ W1 (natural [D][F]) -> gelu -> h16 ----
__global__ __launch_bounds__(256, 2)
void moe_mma0(const float* __restrict__ biasAll) {
    extern __shared__ char sm[];
    const uint32_t sb = smem_u32(sm);
    const int tid = threadIdx.x, wid = tid >> 5, lane = tid & 31;
    const int e = blockIdx.z, m0 = blockIdx.y * 128, n0 = blockIdx.x * 128;
    const int wm = (wid & 1) * 64, wn = (wid >> 1) * 32;

    const __half* Ag = g_x16 + (size_t)e * K_CAP * D_DIM;
    const __half* Bg = g_w1c + (size_t)e * D_DIM * F_DIM;

    float acc[4][4][4];
#pragma unroll
    for (int i = 0; i < 4; i++)
#pragma unroll
        for (int jj = 0; jj < 4; jj++)
#pragma unroll
            for (int q = 0; q < 4; q++) acc[i][jj][q] = 0.f;

    gemm_mainloop<D_DIM, F_DIM>(Ag, Bg, m0, n0, sb, tid, wid, lane, acc);

    const int gid = lane >> 2, tig = lane & 3;
    const float* bias = biasAll + (size_t)e * F_DIM;
#pragma unroll
    for (int mt = 0; mt < 4; mt++) {
#pragma unroll
        for (int half = 0; half < 2; half++) {
            int row = m0 + wm + mt * 16 + gid + half * 8;
            __half* ph = g_h16 + ((size_t)e * K_CAP + row) * F_DIM;
#pragma unroll
            for (int nt = 0; nt < 4; nt++) {
                int col = n0 + wn + nt * 8 + tig * 2;
                float v0 = gelu_tanh(acc[mt][nt][half * 2 + 0] + bias[col]);
                float v1 = gelu_tanh(acc[mt][nt][half * 2 + 1] + bias[col + 1]);
                *(uint32_t*)(ph + col) = pack_h2(v0, v1);
            }
        }
    }
}

// ---- GEMM2: h16 @ W2 (natural [F][D]) -> *val -> scatter-add ----
__global__ __launch_bounds__(256, 2)
void moe_mma1(const float* __restrict__ biasAll, float* __restrict__ outFinal) {
    extern __shared__ char sm[];
    const uint32_t sb = smem_u32(sm);
    const int tid = threadIdx.x, wid = tid >> 5, lane = tid & 31;
    const int e = blockIdx.z, m0 = blockIdx.y * 128, n0 = blockIdx.x * 128;
    const int wm = (wid & 1) * 64, wn = (wid >> 1) * 32;

    const __half* Ag = g_h16 + (size_t)e * K_CAP * F_DIM;
    const __half* Bg = g_w2c + (size_t)e * F_DIM * D_DIM;

    float acc[4][4][4];
#pragma unroll
    for (int i = 0; i < 4; i++)
#pragma unroll
        for (int jj = 0; jj < 4; jj++)
#pragma unroll
            for (int q = 0; q < 4; q++) acc[i][jj][q] = 0.f;

    gemm_mainloop<F_DIM, D_DIM>(Ag, Bg, m0, n0, sb, tid, wid, lane, acc);

    const int gid = lane >> 2, tig = lane & 3;
    const float* bias = biasAll + (size_t)e * D_DIM;
#pragma unroll
    for (int mt = 0; mt < 4; mt++) {
#pragma unroll
        for (int half = 0; half < 2; half++) {
            int row = m0 + wm + mt * 16 + gid + half * 8;
            const int tok = g_routes[e * K_CAP + row];
            const float scale = g_vals[e * K_CAP + row];
            float* orow = outFinal + (size_t)tok * D_DIM;
#pragma unroll
            for (int nt = 0; nt < 4; nt++) {
                int col = n0 + wn + nt * 8 + tig * 2;
                float v0 = (acc[mt][nt][half * 2 + 0] + bias[col]) * scale;
                float v1 = (acc[mt][nt][half * 2 + 1] + bias[col + 1]) * scale;
                red2(orow + col, v0, v1);
            }
        }
    }
}

extern "C" void kernel_launch(void* const* d_in, const int* in_sizes, int n_in,
                              void* d_out, int out_size) {
    const float* x  = (const float*)d_in[0];
    const float* Ws = (const float*)d_in[1];
    const float* bs = (const float*)d_in[2];
    const float* W1 = (const float*)d_in[3];
    const float* b1 = (const float*)d_in[4];
    const float* W2 = (const float*)d_in[5];
    const float* b2 = (const float*)d_in[6];
    float* out = (float*)d_out;

    cudaFuncSetAttribute(moe_mma0, cudaFuncAttributeMaxDynamicSharedMemorySize, SMEM_BYTES);
    cudaFuncSetAttribute(moe_mma1, cudaFuncAttributeMaxDynamicSharedMemorySize, SMEM_BYTES);

    // phase 1: gating (512) || zero (4096) || conv W1 (4096)
    phase1_kernel<<<512 + 4096 + 4096, 256>>>(x, Ws, bs, (float4*)out, (const float4*)W1);
    // phase 2: topk (8) || conv W2 (2048)
    prep_kernel<<<8 + 2048, 512>>>((const float4*)W2);
    gather_kernel<<<E_NUM * K_CAP, 256>>>(x);
    moe_mma0<<<dim3(F_DIM / 128, K_CAP / 128, E_NUM), 256, SMEM_BYTES>>>(b1);
    moe_mma1<<<dim3(D_DIM / 128, K_CAP / 128, E_NUM), 256, SMEM_BYTES>>>(b2, out);
}